// round 7
// baseline (speedup 1.0000x reference)
#include <cuda_runtime.h>
#include <cuda_bf16.h>
#include <cstdint>

#define TILEM 128
#define NTHR  256
#define NJOBS 18
#define ARS   144      // activation smem row stride (bytes)

// smem byte offsets
#define SM_A0H   0
#define SM_A0L   18432
#define SM_A1H   36864
#define SM_A1L   55296
#define SM_WTAIL 73728
#define SM_MASK  75776
#define SM_INV   76288
#define SM_TOTAL 80384

// fragment-ordered weights: entry = ((job*2 + nhalf)*4 + kc)*32 + lane, 16 uint32 each
// [hi_a(4) hi_b(4) lo_a(4) lo_b(4)]
__device__ __align__(16) uint32_t g_wf[NJOBS * 2 * 4 * 32 * 16];
__device__ float g_bb[NJOBS * 64];
__device__ float g_aw[NJOBS * 64];
__device__ int g_inv[(size_t)262144 * 8];

static __device__ __forceinline__ uint32_t smem_u32(const void* p) {
    uint32_t a;
    asm("{ .reg .u64 t; cvta.to.shared.u64 t, %1; cvt.u32.u64 %0, t; }" : "=r"(a) : "l"(p));
    return a;
}
static __device__ __forceinline__ uint32_t pkbf(__nv_bfloat16 a, __nv_bfloat16 b) {
    uint16_t ua = *(uint16_t*)&a, ub = *(uint16_t*)&b;
    return (uint32_t)ua | ((uint32_t)ub << 16);
}
static __device__ __forceinline__ float upk_lo(uint32_t u) {
    uint16_t t = (uint16_t)u; __nv_bfloat16 b = *(__nv_bfloat16*)&t; return __bfloat162float(b);
}
static __device__ __forceinline__ float upk_hi(uint32_t u) {
    uint16_t t = (uint16_t)(u >> 16); __nv_bfloat16 b = *(__nv_bfloat16*)&t; return __bfloat162float(b);
}
static __device__ __forceinline__ void spl(float v, __nv_bfloat16& h, __nv_bfloat16& l) {
    h = __float2bfloat16(v);
    l = __float2bfloat16(v - __bfloat162float(h));
}
static __device__ __forceinline__ void mma_bf16(float* c, const uint32_t* a, const uint32_t* b) {
    asm volatile(
        "mma.sync.aligned.m16n8k16.row.col.f32.bf16.bf16.f32 "
        "{%0,%1,%2,%3}, {%4,%5,%6,%7}, {%8,%9}, {%0,%1,%2,%3};"
        : "+f"(c[0]), "+f"(c[1]), "+f"(c[2]), "+f"(c[3])
        : "r"(a[0]), "r"(a[1]), "r"(a[2]), "r"(a[3]), "r"(b[0]), "r"(b[1]));
}
static __device__ __forceinline__ void ldm4(uint32_t* r, uint32_t addr) {
    asm volatile("ldmatrix.sync.aligned.m8n8.x4.shared.b16 {%0,%1,%2,%3}, [%4];"
        : "=r"(r[0]), "=r"(r[1]), "=r"(r[2]), "=r"(r[3]) : "r"(addr));
}

// ---------------- K_prep: weights -> bf16 hi/lo fragment order; bias tables ----------------
__global__ void k_prep(const float* __restrict__ Wd1, const float* __restrict__ Wd2,
                       const float* __restrict__ Wp1, const float* __restrict__ Wp2,
                       const float* __restrict__ Wu1, const float* __restrict__ Wu2,
                       const float* __restrict__ Wu3, const float* __restrict__ Wu4,
                       const float* __restrict__ bd1, const float* __restrict__ bd2,
                       const float* __restrict__ bp1, const float* __restrict__ bp2,
                       const float* __restrict__ bu1, const float* __restrict__ bu2,
                       const float* __restrict__ bu3, const float* __restrict__ bu4,
                       const float* __restrict__ ad,  const float* __restrict__ ap_,
                       const float* __restrict__ au1, const float* __restrict__ au2) {
    int j = blockIdx.x;
    int t = threadIdx.x;

    auto getw = [&](int k, int n) -> float {   // source row k (0..63), job-local col n (0..63)
        if (j == 0)      return Wd1[k * 64 + n];
        else if (j == 1) return Wd2[k * 64 + n];
        else if (j == 2) return Wp1[k * 64 + n];
        else if (j <= 6) { int ng = (j - 3) * 64 + n; return (ng < 255) ? Wp2[k * 255 + ng] : 0.f; }
        else if (j == 7) return Wu1[k * 64 + n];
        else if (j == 8) return Wu2[k * 64 + n];
        else if (j == 9) return Wu3[k * 64 + n];
        else             return Wu4[(size_t)k * 512 + (j - 10) * 64 + n];
    };

    // one fragment entry per thread: p = t>>7, kc = (t>>5)&3, lane = t&31
    {
        int p = t >> 7, kc = (t >> 5) & 3, lane = t & 31;
        int q = lane >> 2, r2 = (lane & 3) * 2;
        uint32_t out[16];
#pragma unroll
        for (int nb = 0; nb < 4; nb++) {
            int n = p * 32 + nb * 8 + q;
            int k0 = kc * 16 + r2;
            float v00 = getw(k0, n),     v01 = getw(k0 + 1, n);
            float v10 = getw(k0 + 8, n), v11 = getw(k0 + 9, n);
            __nv_bfloat16 h00, h01, h10, h11, l00, l01, l10, l11;
            spl(v00, h00, l00); spl(v01, h01, l01);
            spl(v10, h10, l10); spl(v11, h11, l11);
            int half = nb >> 1, sub = nb & 1;
            out[half * 4 + sub * 2 + 0]     = pkbf(h00, h01);
            out[half * 4 + sub * 2 + 1]     = pkbf(h10, h11);
            out[8 + half * 4 + sub * 2 + 0] = pkbf(l00, l01);
            out[8 + half * 4 + sub * 2 + 1] = pkbf(l10, l11);
        }
        uint4* dst = (uint4*)(g_wf + (size_t)(((j * 2 + p) * 4 + kc) * 32 + lane) * 16);
        dst[0] = make_uint4(out[0], out[1], out[2], out[3]);
        dst[1] = make_uint4(out[4], out[5], out[6], out[7]);
        dst[2] = make_uint4(out[8], out[9], out[10], out[11]);
        dst[3] = make_uint4(out[12], out[13], out[14], out[15]);
    }

    if (t < 64) {
        int c = t; float b = 0.f, a = 0.f;
        switch (j) {
            case 0: b = bd1[c]; a = ad[c]; break;
            case 1: b = bd2[c]; break;
            case 2: b = bp1[c]; a = ap_[c]; break;
            case 3: case 4: case 5: case 6: {
                int ng = (j - 3) * 64 + c; b = (ng < 255) ? bp2[ng] : 0.f; break; }
            case 7: b = bu1[c]; a = au1[c]; break;
            case 8: b = bu2[c]; a = au2[c]; break;
            case 9: b = bu3[c]; break;
            default: b = bu4[(j - 10) * 64 + c]; break;
        }
        g_bb[j * 64 + c] = b;
        g_aw[j * 64 + c] = a;
    }
}

// ---------------- K0: inverse map of sel_idx ----------------
__global__ void k0_inv(const int* __restrict__ sel, int M) {
    int m = blockIdx.x * 256 + threadIdx.x;
    if (m < M) g_inv[sel[m]] = m;
}

// ---------------- fused main kernel ----------------
__global__ __launch_bounds__(NTHR, 2)
void k_main(const float* __restrict__ X, const int* __restrict__ bin,
            const float* __restrict__ Wu1,
            float* __restrict__ pred, float* __restrict__ oct, float* __restrict__ newF) {
    extern __shared__ char smem[];
    const uint32_t sb = smem_u32(smem);
    int tid = threadIdx.x;
    int wid = tid >> 5, lane = tid & 31;
    int g = lane >> 2, tg = lane & 3;
    int mrow = (wid >> 1) * 32;       // 4 m-quarters
    int p = wid & 1;                  // n-half
    int ncol = p * 32;
    int base = blockIdx.x * TILEM;

    float* wtail = (float*)(smem + SM_WTAIL);
    int*   smask = (int*)(smem + SM_MASK);
    int*   sinv  = (int*)(smem + SM_INV);

    // ---- prologue: X -> R0 (split bf16), mask/inv/oct, Wu1 tail ----
    {
        const float4* Xr = (const float4*)(X + (size_t)base * 64);
#pragma unroll
        for (int it = 0; it < 8; it++) {
            int idx = it * NTHR + tid;            // 0..2047 float4s
            int row = idx >> 4, q = idx & 15;
            float4 v = Xr[idx];
            __nv_bfloat16 h0, h1, h2, h3, l0, l1, l2, l3;
            spl(v.x, h0, l0); spl(v.y, h1, l1); spl(v.z, h2, l2); spl(v.w, h3, l3);
            *(uint2*)(smem + SM_A0H + row * ARS + q * 8) = make_uint2(pkbf(h0, h1), pkbf(h2, h3));
            *(uint2*)(smem + SM_A0L + row * ARS + q * 8) = make_uint2(pkbf(l0, l1), pkbf(l2, l3));
        }
        if (tid < TILEM) {
            const int* bp = bin + (size_t)(base + tid) * 8;
            int4 b0 = *(const int4*)bp;
            int4 b1 = *(const int4*)(bp + 4);
            int m = (b0.x != 0) | ((b0.y != 0) << 1) | ((b0.z != 0) << 2) | ((b0.w != 0) << 3)
                  | ((b1.x != 0) << 4) | ((b1.y != 0) << 5) | ((b1.z != 0) << 6) | ((b1.w != 0) << 7);
            smask[tid] = m;
            oct[base + tid] = (float)(m - 1);
            const int* ip = g_inv + (size_t)(base + tid) * 8;
            int4 i0 = *(const int4*)ip;
            int4 i1 = *(const int4*)(ip + 4);
            *(int4*)(sinv + tid * 8)     = i0;
            *(int4*)(sinv + tid * 8 + 4) = i1;
        }
#pragma unroll
        for (int it = 0; it < 2; it++)
            wtail[it * NTHR + tid] = Wu1[4096 + it * NTHR + tid];
    }
    __syncthreads();

    // ldmatrix lane base offset for A
    uint32_t aoff = (uint32_t)((mrow + (lane & 7) + ((lane >> 3) & 1) * 8) * ARS
                              + ((lane >> 4) & 1) * 16);

    for (int j = 0; j < NJOBS; j++) {
        // sync only on true activation RAW hazards: jobs 1,2,3,7,8,9,10
        if ((0x78Eu >> j) & 1) __syncthreads();

        // ---- GEMM: 3-term bf16-split, fp32 accum; warp tile m32 x n32 ----
        bool aR0 = (j == 0) | (j == 2) | (j == 7) | (j == 9);
        uint32_t aHb = sb + (aR0 ? SM_A0H : SM_A1H) + aoff;
        uint32_t aLb = aHb + 18432;

        const uint4* wp = (const uint4*)g_wf + (size_t)(((j * 2 + p) * 4) * 32 + lane) * 4;

        float acc[2][4][4];
#pragma unroll
        for (int mt = 0; mt < 2; mt++)
#pragma unroll
            for (int nt = 0; nt < 4; nt++)
#pragma unroll
                for (int i = 0; i < 4; i++) acc[mt][nt][i] = 0.f;

        uint4 ha = wp[0], hb = wp[1], la = wp[2], lb = wp[3];
#pragma unroll
        for (int kc = 0; kc < 4; kc++) {
            uint4 nha, nhb, nla, nlb;
            if (kc < 3) {
                const uint4* np = wp + (kc + 1) * 128;
                nha = np[0]; nhb = np[1]; nla = np[2]; nlb = np[3];
            }
            uint32_t ko = kc * 32;
            uint32_t ah[2][4], al[2][4];
            ldm4(ah[0], aHb + ko); ldm4(ah[1], aHb + ko + 16 * ARS);
            ldm4(al[0], aLb + ko); ldm4(al[1], aLb + ko + 16 * ARS);
            uint32_t bhf[8] = {ha.x, ha.y, ha.z, ha.w, hb.x, hb.y, hb.z, hb.w};
            uint32_t blf[8] = {la.x, la.y, la.z, la.w, lb.x, lb.y, lb.z, lb.w};
#pragma unroll
            for (int nt = 0; nt < 4; nt++) {
                const uint32_t* Bh = &bhf[nt * 2];
                const uint32_t* Bl = &blf[nt * 2];
#pragma unroll
                for (int mt = 0; mt < 2; mt++) {
                    float* c = acc[mt][nt];
                    mma_bf16(c, ah[mt], Bh);
                    mma_bf16(c, ah[mt], Bl);
                    mma_bf16(c, al[mt], Bh);
                }
            }
            if (kc < 3) { ha = nha; hb = nhb; la = nla; lb = nlb; }
        }

        // ---- epilogue ----
        const float* bb = g_bb + j * 64;
#pragma unroll
        for (int nt = 0; nt < 4; nt++) {
            int col = ncol + nt * 8 + tg * 2;
            float2 bv = __ldg((const float2*)(bb + col));
#pragma unroll
            for (int mt = 0; mt < 2; mt++) {
                float* c = acc[mt][nt];
                c[0] += bv.x; c[1] += bv.y; c[2] += bv.x; c[3] += bv.y;
            }
        }

        if (j == 7) {   // bin-concat tail: + 256 * Wu1[64+jj][col] for set bits (exact)
#pragma unroll
            for (int mt = 0; mt < 2; mt++) {
                int rA = mrow + mt * 16 + g;
                int mA = smask[rA], mB = smask[rA + 8];
#pragma unroll
                for (int jj = 0; jj < 8; jj++) {
                    bool bA = (mA >> jj) & 1, bB = (mB >> jj) & 1;
                    if (bA | bB) {
#pragma unroll
                        for (int nt = 0; nt < 4; nt++) {
                            float2 tv = *(const float2*)(wtail + jj * 64 + ncol + nt * 8 + tg * 2);
                            float* c = acc[mt][nt];
                            if (bA) { c[0] += 256.f * tv.x; c[1] += 256.f * tv.y; }
                            if (bB) { c[2] += 256.f * tv.x; c[3] += 256.f * tv.y; }
                        }
                    }
                }
            }
        }
        if (j == 0 || j == 2 || j == 7 || j == 8) {  // prelu
            const float* aw = g_aw + j * 64;
#pragma unroll
            for (int nt = 0; nt < 4; nt++) {
                int col = ncol + nt * 8 + tg * 2;
                float2 av = __ldg((const float2*)(aw + col));
#pragma unroll
                for (int mt = 0; mt < 2; mt++) {
                    float* c = acc[mt][nt];
                    c[0] = c[0] >= 0.f ? c[0] : av.x * c[0];
                    c[1] = c[1] >= 0.f ? c[1] : av.y * c[1];
                    c[2] = c[2] >= 0.f ? c[2] : av.x * c[2];
                    c[3] = c[3] >= 0.f ? c[3] : av.y * c[3];
                }
            }
        }
        if (j == 1 || j == 9) {  // residual (j1: +X in R0; j9: +u1 in R1), per-thread positions
            const char* rH = smem + (j == 1 ? SM_A0H : SM_A1H);
            const char* rL = rH + 18432;
#pragma unroll
            for (int mt = 0; mt < 2; mt++) {
                int r = mrow + mt * 16 + g;
#pragma unroll
                for (int nt = 0; nt < 4; nt++) {
                    uint32_t off0 = r * ARS + (ncol + nt * 8 + tg * 2) * 2;
                    uint32_t off1 = off0 + 8 * ARS;
                    uint32_t h0 = *(const uint32_t*)(rH + off0), l0 = *(const uint32_t*)(rL + off0);
                    uint32_t h1 = *(const uint32_t*)(rH + off1), l1 = *(const uint32_t*)(rL + off1);
                    float* c = acc[mt][nt];
                    c[0] += upk_lo(h0) + upk_lo(l0);
                    c[1] += upk_hi(h0) + upk_hi(l0);
                    c[2] += upk_lo(h1) + upk_lo(l1);
                    c[3] += upk_hi(h1) + upk_hi(l1);
                }
            }
        }

        if (j >= 3 && j <= 6) {
            // pred -> gmem; stride 255 floats is odd -> scalar 4B stores
            int o0 = (j - 3) * 64;
#pragma unroll
            for (int mt = 0; mt < 2; mt++) {
                int r = base + mrow + mt * 16 + g;
#pragma unroll
                for (int nt = 0; nt < 4; nt++) {
                    int col = o0 + ncol + nt * 8 + tg * 2;
                    float* c = acc[mt][nt];
                    float* p0 = pred + (size_t)r * 255 + col;
                    float* p1 = pred + (size_t)(r + 8) * 255 + col;
                    if (col < 255) { p0[0] = c[0]; p1[0] = c[2]; }
                    if (col + 1 < 255) { p0[1] = c[1]; p1[1] = c[3]; }
                }
            }
        } else if (j >= 10) {
            // child scatter -> newF (stride 64 floats: float2 aligned)
            int ch = j - 10;
#pragma unroll
            for (int mt = 0; mt < 2; mt++) {
                int rA = mrow + mt * 16 + g;
                bool okA = (smask[rA] >> ch) & 1, okB = (smask[rA + 8] >> ch) & 1;
                int iA = sinv[rA * 8 + ch], iB = sinv[(rA + 8) * 8 + ch];
#pragma unroll
                for (int nt = 0; nt < 4; nt++) {
                    int col = ncol + nt * 8 + tg * 2;
                    float* c = acc[mt][nt];
                    if (okA) *(float2*)(newF + (size_t)iA * 64 + col) = make_float2(c[0], c[1]);
                    if (okB) *(float2*)(newF + (size_t)iB * 64 + col) = make_float2(c[2], c[3]);
                }
            }
        } else {
            // activation job: split-store to dst region (j1,j8 -> R0 else R1)
            bool dR0 = (j == 1) | (j == 8);
            char* dH = smem + (dR0 ? SM_A0H : SM_A1H);
            char* dL = dH + 18432;
#pragma unroll
            for (int mt = 0; mt < 2; mt++) {
                int r = mrow + mt * 16 + g;
#pragma unroll
                for (int nt = 0; nt < 4; nt++) {
                    uint32_t off0 = r * ARS + (ncol + nt * 8 + tg * 2) * 2;
                    uint32_t off1 = off0 + 8 * ARS;
                    float* c = acc[mt][nt];
                    __nv_bfloat16 h0, h1, h2, h3, l0, l1, l2, l3;
                    spl(c[0], h0, l0); spl(c[1], h1, l1);
                    spl(c[2], h2, l2); spl(c[3], h3, l3);
                    *(uint32_t*)(dH + off0) = pkbf(h0, h1);
                    *(uint32_t*)(dL + off0) = pkbf(l0, l1);
                    *(uint32_t*)(dH + off1) = pkbf(h2, h3);
                    *(uint32_t*)(dL + off1) = pkbf(l2, l3);
                }
            }
        }
    }
}

extern "C" void kernel_launch(void* const* d_in, const int* in_sizes, int n_in,
                              void* d_out, int out_size) {
    const float* X   = (const float*)d_in[0];
    const int*   bin = (const int*)d_in[1];
    const int*   sel = (const int*)d_in[2];
    const float* Wd1 = (const float*)d_in[3];
    const float* bd1 = (const float*)d_in[4];
    const float* ad  = (const float*)d_in[5];
    const float* Wd2 = (const float*)d_in[6];
    const float* bd2 = (const float*)d_in[7];
    const float* Wp1 = (const float*)d_in[8];
    const float* bp1 = (const float*)d_in[9];
    const float* ap  = (const float*)d_in[10];
    const float* Wp2 = (const float*)d_in[11];
    const float* bp2 = (const float*)d_in[12];
    const float* Wu1 = (const float*)d_in[13];
    const float* bu1 = (const float*)d_in[14];
    const float* au1 = (const float*)d_in[15];
    const float* Wu2 = (const float*)d_in[16];
    const float* bu2 = (const float*)d_in[17];
    const float* au2 = (const float*)d_in[18];
    const float* Wu3 = (const float*)d_in[19];
    const float* bu3 = (const float*)d_in[20];
    const float* Wu4 = (const float*)d_in[21];
    const float* bu4 = (const float*)d_in[22];

    int n = in_sizes[0] / 64;
    int M = in_sizes[2];
    float* newF = (float*)d_out;
    float* pred = newF + (size_t)M * 64;
    float* oct  = pred + (size_t)n * 255;

    cudaFuncSetAttribute(k_main, cudaFuncAttributeMaxDynamicSharedMemorySize, SM_TOTAL);

    k_prep<<<NJOBS, 256>>>(Wd1, Wd2, Wp1, Wp2, Wu1, Wu2, Wu3, Wu4,
                           bd1, bd2, bp1, bp2, bu1, bu2, bu3, bu4,
                           ad, ap, au1, au2);
    if (M > 0) k0_inv<<<(M + 255) / 256, 256>>>(sel, M);
    k_main<<<n / TILEM, NTHR, SM_TOTAL>>>(X, bin, Wu1, pred, oct, newF);
}

// round 8
// speedup vs baseline: 1.2435x; 1.2435x over previous
#include <cuda_runtime.h>
#include <cuda_bf16.h>
#include <cstdint>

#define TILEM 128
#define NTHR  256
#define NJOBS 18
#define ARS   144      // smem row stride (bytes)

// smem byte offsets
#define SM_A0H   0
#define SM_A0L   18432
#define SM_A1H   36864
#define SM_A1L   55296
#define SM_W     73728   // two W buffers, 18432 B each: [hi 9216 | lo 9216]
#define SM_WTAIL 110592
#define SM_MASK  112640
#define SM_TOTAL 113152

// pre-split weights, [job][n][k] 64x64 bf16
__device__ __align__(16) __nv_bfloat16 g_wh[NJOBS * 4096];
__device__ __align__(16) __nv_bfloat16 g_wl[NJOBS * 4096];
__device__ float g_bb[NJOBS * 64];
__device__ float g_aw[NJOBS * 64];
__device__ int g_inv[(size_t)262144 * 8];

static __device__ __forceinline__ uint32_t smem_u32(const void* p) {
    uint32_t a;
    asm("{ .reg .u64 t; cvta.to.shared.u64 t, %1; cvt.u32.u64 %0, t; }" : "=r"(a) : "l"(p));
    return a;
}
static __device__ __forceinline__ uint32_t pkbf(__nv_bfloat16 a, __nv_bfloat16 b) {
    uint16_t ua = *(uint16_t*)&a, ub = *(uint16_t*)&b;
    return (uint32_t)ua | ((uint32_t)ub << 16);
}
static __device__ __forceinline__ float upk_lo(uint32_t u) {
    uint16_t t = (uint16_t)u; __nv_bfloat16 b = *(__nv_bfloat16*)&t; return __bfloat162float(b);
}
static __device__ __forceinline__ float upk_hi(uint32_t u) {
    uint16_t t = (uint16_t)(u >> 16); __nv_bfloat16 b = *(__nv_bfloat16*)&t; return __bfloat162float(b);
}
static __device__ __forceinline__ void spl(float v, __nv_bfloat16& h, __nv_bfloat16& l) {
    h = __float2bfloat16(v);
    l = __float2bfloat16(v - __bfloat162float(h));
}
static __device__ __forceinline__ void mma_bf16(float* c, const uint32_t* a, const uint32_t* b) {
    asm volatile(
        "mma.sync.aligned.m16n8k16.row.col.f32.bf16.bf16.f32 "
        "{%0,%1,%2,%3}, {%4,%5,%6,%7}, {%8,%9}, {%0,%1,%2,%3};"
        : "+f"(c[0]), "+f"(c[1]), "+f"(c[2]), "+f"(c[3])
        : "r"(a[0]), "r"(a[1]), "r"(a[2]), "r"(a[3]), "r"(b[0]), "r"(b[1]));
}
static __device__ __forceinline__ void ldm4(uint32_t* r, uint32_t addr) {
    asm volatile("ldmatrix.sync.aligned.m8n8.x4.shared.b16 {%0,%1,%2,%3}, [%4];"
        : "=r"(r[0]), "=r"(r[1]), "=r"(r[2]), "=r"(r[3]) : "r"(addr));
}

// ---------------- K_prep: split weights to bf16 hi/lo + bias/prelu tables ----------------
__global__ void k_prep(const float* __restrict__ Wd1, const float* __restrict__ Wd2,
                       const float* __restrict__ Wp1, const float* __restrict__ Wp2,
                       const float* __restrict__ Wu1, const float* __restrict__ Wu2,
                       const float* __restrict__ Wu3, const float* __restrict__ Wu4,
                       const float* __restrict__ bd1, const float* __restrict__ bd2,
                       const float* __restrict__ bp1, const float* __restrict__ bp2,
                       const float* __restrict__ bu1, const float* __restrict__ bu2,
                       const float* __restrict__ bu3, const float* __restrict__ bu4,
                       const float* __restrict__ ad,  const float* __restrict__ ap_,
                       const float* __restrict__ au1, const float* __restrict__ au2) {
    int j = blockIdx.x;
    for (int t = threadIdx.x; t < 4096; t += 256) {
        int n = t >> 6, k = t & 63;
        float v;
        if (j == 0)      v = Wd1[k * 64 + n];
        else if (j == 1) v = Wd2[k * 64 + n];
        else if (j == 2) v = Wp1[k * 64 + n];
        else if (j <= 6) { int ng = (j - 3) * 64 + n; v = (ng < 255) ? Wp2[k * 255 + ng] : 0.f; }
        else if (j == 7) v = Wu1[k * 64 + n];
        else if (j == 8) v = Wu2[k * 64 + n];
        else if (j == 9) v = Wu3[k * 64 + n];
        else             v = Wu4[(size_t)k * 512 + (j - 10) * 64 + n];
        __nv_bfloat16 h, l; spl(v, h, l);
        g_wh[j * 4096 + t] = h;
        g_wl[j * 4096 + t] = l;
    }
    int t = threadIdx.x;
    if (t < 64) {
        int c = t; float b = 0.f, a = 0.f;
        switch (j) {
            case 0: b = bd1[c]; a = ad[c]; break;
            case 1: b = bd2[c]; break;
            case 2: b = bp1[c]; a = ap_[c]; break;
            case 3: case 4: case 5: case 6: {
                int ng = (j - 3) * 64 + c; b = (ng < 255) ? bp2[ng] : 0.f; break; }
            case 7: b = bu1[c]; a = au1[c]; break;
            case 8: b = bu2[c]; a = au2[c]; break;
            case 9: b = bu3[c]; break;
            default: b = bu4[(j - 10) * 64 + c]; break;
        }
        g_bb[j * 64 + c] = b;
        g_aw[j * 64 + c] = a;
    }
}

// ---------------- K0: inverse map of sel_idx ----------------
__global__ void k0_inv(const int* __restrict__ sel, int M) {
    int m = blockIdx.x * 256 + threadIdx.x;
    if (m < M) g_inv[sel[m]] = m;
}

// ---------------- fused main kernel ----------------
__global__ __launch_bounds__(NTHR, 2)
void k_main(const float* __restrict__ X, const int* __restrict__ bin,
            const float* __restrict__ Wu1,
            float* __restrict__ pred, float* __restrict__ oct, float* __restrict__ newF) {
    extern __shared__ char smem[];
    const uint32_t sb = smem_u32(smem);
    int tid = threadIdx.x;
    int wid = tid >> 5, lane = tid & 31;
    int g = lane >> 2, tg = lane & 3;
    int mrow = (wid >> 1) * 32;       // 4 m-quarters
    int ncol = (wid & 1) * 32;        // 2 n-halves
    int base = blockIdx.x * TILEM;

    float* wtail = (float*)(smem + SM_WTAIL);
    int*   smask = (int*)(smem + SM_MASK);

    // ---- prologue: X -> R0 (split bf16), mask/oct, Wu1 tail ----
    {
        const float4* Xr = (const float4*)(X + (size_t)base * 64);
#pragma unroll
        for (int it = 0; it < 8; it++) {
            int idx = it * NTHR + tid;            // 0..2047 float4s
            int row = idx >> 4, q = idx & 15;
            float4 v = Xr[idx];
            __nv_bfloat16 h0, h1, h2, h3, l0, l1, l2, l3;
            spl(v.x, h0, l0); spl(v.y, h1, l1); spl(v.z, h2, l2); spl(v.w, h3, l3);
            *(uint2*)(smem + SM_A0H + row * ARS + q * 8) = make_uint2(pkbf(h0, h1), pkbf(h2, h3));
            *(uint2*)(smem + SM_A0L + row * ARS + q * 8) = make_uint2(pkbf(l0, l1), pkbf(l2, l3));
        }
        if (tid < TILEM) {
            const int* bp = bin + (size_t)(base + tid) * 8;
            int4 b0 = *(const int4*)bp;
            int4 b1 = *(const int4*)(bp + 4);
            int m = (b0.x != 0) | ((b0.y != 0) << 1) | ((b0.z != 0) << 2) | ((b0.w != 0) << 3)
                  | ((b1.x != 0) << 4) | ((b1.y != 0) << 5) | ((b1.z != 0) << 6) | ((b1.w != 0) << 7);
            smask[tid] = m;
            oct[base + tid] = (float)(m - 1);
        }
#pragma unroll
        for (int it = 0; it < 2; it++)
            wtail[it * NTHR + tid] = Wu1[4096 + it * NTHR + tid];
    }

    // ---- W pipeline prologue: commit job 0 to buf0, prefetch job 1 ----
    uint4 wr0, wr1, wr2, wr3;
    {
        const uint4* sh = (const uint4*)(g_wh);
        const uint4* sl = (const uint4*)(g_wl);
        wr0 = sh[tid]; wr1 = sh[tid + 256];
        wr2 = sl[tid]; wr3 = sl[tid + 256];
        int i0 = tid, i1 = tid + 256;
        char* buf = smem + SM_W;   // buf0
        *(uint4*)(buf + (i0 >> 3) * ARS + (i0 & 7) * 16)        = wr0;
        *(uint4*)(buf + (i1 >> 3) * ARS + (i1 & 7) * 16)        = wr1;
        *(uint4*)(buf + 9216 + (i0 >> 3) * ARS + (i0 & 7) * 16) = wr2;
        *(uint4*)(buf + 9216 + (i1 >> 3) * ARS + (i1 & 7) * 16) = wr3;
        const uint4* sh1 = (const uint4*)(g_wh + 4096);
        const uint4* sl1 = (const uint4*)(g_wl + 4096);
        wr0 = sh1[tid]; wr1 = sh1[tid + 256];
        wr2 = sl1[tid]; wr3 = sl1[tid + 256];
    }
    __syncthreads();

    // ldmatrix lane base offsets
    uint32_t aoff = (uint32_t)((mrow + (lane & 7) + ((lane >> 3) & 1) * 8) * ARS
                              + ((lane >> 4) & 1) * 16);
    uint32_t woff = (uint32_t)((ncol + (lane & 7) + ((lane >> 4) & 1) * 8) * ARS
                              + ((lane >> 3) & 1) * 16);

    for (int j = 0; j < NJOBS; j++) {
        // buf[j&1] holds W_j (committed in previous iteration / prologue).
        // Commit W_{j+1} (in regs) into buf[(j+1)&1]; prefetch W_{j+2}.
        if (j + 1 < NJOBS) {
            char* buf = smem + SM_W + ((j + 1) & 1) * 18432;
            int i0 = tid, i1 = tid + 256;
            *(uint4*)(buf + (i0 >> 3) * ARS + (i0 & 7) * 16)        = wr0;
            *(uint4*)(buf + (i1 >> 3) * ARS + (i1 & 7) * 16)        = wr1;
            *(uint4*)(buf + 9216 + (i0 >> 3) * ARS + (i0 & 7) * 16) = wr2;
            *(uint4*)(buf + 9216 + (i1 >> 3) * ARS + (i1 & 7) * 16) = wr3;
        }
        if (j + 2 < NJOBS) {
            const uint4* sh = (const uint4*)(g_wh + (j + 2) * 4096);
            const uint4* sl = (const uint4*)(g_wl + (j + 2) * 4096);
            wr0 = sh[tid]; wr1 = sh[tid + 256];
            wr2 = sl[tid]; wr3 = sl[tid + 256];
        }

        // ---- GEMM: 3-term bf16-split, fp32 accum; warp tile m32 x n32 ----
        bool aR0 = (j == 0) | (j == 2) | (j == 7) | (j == 9);
        uint32_t aHb = sb + (aR0 ? SM_A0H : SM_A1H) + aoff;
        uint32_t aLb = aHb + 18432;
        uint32_t wHb = sb + SM_W + (j & 1) * 18432 + woff;
        uint32_t wLb = wHb + 9216;

        float acc[2][4][4];
#pragma unroll
        for (int mt = 0; mt < 2; mt++)
#pragma unroll
            for (int nt = 0; nt < 4; nt++)
#pragma unroll
                for (int i = 0; i < 4; i++) acc[mt][nt][i] = 0.f;

#pragma unroll
        for (int kc = 0; kc < 4; kc++) {
            uint32_t ko = kc * 32;
            uint32_t ah[2][4], al[2][4], bh[2][4], bl[2][4];
            ldm4(ah[0], aHb + ko); ldm4(ah[1], aHb + ko + 16 * ARS);
            ldm4(al[0], aLb + ko); ldm4(al[1], aLb + ko + 16 * ARS);
            ldm4(bh[0], wHb + ko); ldm4(bh[1], wHb + ko + 16 * ARS);
            ldm4(bl[0], wLb + ko); ldm4(bl[1], wLb + ko + 16 * ARS);
#pragma unroll
            for (int p2 = 0; p2 < 2; p2++)
#pragma unroll
                for (int h = 0; h < 2; h++) {
                    int nt = p2 * 2 + h;
                    const uint32_t* Bh = &bh[p2][h * 2];
                    const uint32_t* Bl = &bl[p2][h * 2];
#pragma unroll
                    for (int mt = 0; mt < 2; mt++) {
                        float* c = acc[mt][nt];
                        mma_bf16(c, ah[mt], Bh);
                        mma_bf16(c, ah[mt], Bl);
                        mma_bf16(c, al[mt], Bh);
                    }
                }
        }

        // ---- epilogue ----
        const float* bb = g_bb + j * 64;
#pragma unroll
        for (int nt = 0; nt < 4; nt++) {
            int col = ncol + nt * 8 + tg * 2;
            float2 bv = __ldg((const float2*)(bb + col));
#pragma unroll
            for (int mt = 0; mt < 2; mt++) {
                float* c = acc[mt][nt];
                c[0] += bv.x; c[1] += bv.y; c[2] += bv.x; c[3] += bv.y;
            }
        }

        if (j == 7) {   // bin-concat tail: + 256 * Wu1[64+jj][col] for set bits (exact)
#pragma unroll
            for (int mt = 0; mt < 2; mt++) {
                int rA = mrow + mt * 16 + g;
                int mA = smask[rA], mB = smask[rA + 8];
#pragma unroll
                for (int jj = 0; jj < 8; jj++) {
                    bool bA = (mA >> jj) & 1, bB = (mB >> jj) & 1;
                    if (bA | bB) {
#pragma unroll
                        for (int nt = 0; nt < 4; nt++) {
                            float2 t = *(const float2*)(wtail + jj * 64 + ncol + nt * 8 + tg * 2);
                            float* c = acc[mt][nt];
                            if (bA) { c[0] += 256.f * t.x; c[1] += 256.f * t.y; }
                            if (bB) { c[2] += 256.f * t.x; c[3] += 256.f * t.y; }
                        }
                    }
                }
            }
        }
        if (j == 0 || j == 2 || j == 7 || j == 8) {  // prelu
            const float* aw = g_aw + j * 64;
#pragma unroll
            for (int nt = 0; nt < 4; nt++) {
                int col = ncol + nt * 8 + tg * 2;
                float2 av = __ldg((const float2*)(aw + col));
#pragma unroll
                for (int mt = 0; mt < 2; mt++) {
                    float* c = acc[mt][nt];
                    c[0] = c[0] >= 0.f ? c[0] : av.x * c[0];
                    c[1] = c[1] >= 0.f ? c[1] : av.y * c[1];
                    c[2] = c[2] >= 0.f ? c[2] : av.x * c[2];
                    c[3] = c[3] >= 0.f ? c[3] : av.y * c[3];
                }
            }
        }
        if (j == 1 || j == 9) {  // residual (j1: +X in R0; j9: +u1 in R1)
            const char* rH = smem + (j == 1 ? SM_A0H : SM_A1H);
            const char* rL = rH + 18432;
#pragma unroll
            for (int mt = 0; mt < 2; mt++) {
                int r = mrow + mt * 16 + g;
#pragma unroll
                for (int nt = 0; nt < 4; nt++) {
                    uint32_t off0 = r * ARS + (ncol + nt * 8 + tg * 2) * 2;
                    uint32_t off1 = off0 + 8 * ARS;
                    uint32_t h0 = *(const uint32_t*)(rH + off0), l0 = *(const uint32_t*)(rL + off0);
                    uint32_t h1 = *(const uint32_t*)(rH + off1), l1 = *(const uint32_t*)(rL + off1);
                    float* c = acc[mt][nt];
                    c[0] += upk_lo(h0) + upk_lo(l0);
                    c[1] += upk_hi(h0) + upk_hi(l0);
                    c[2] += upk_lo(h1) + upk_lo(l1);
                    c[3] += upk_hi(h1) + upk_hi(l1);
                }
            }
        }

        if (j >= 3 && j <= 6) {
            // pred -> gmem; stride 255 floats is odd -> scalar 4B stores
            int o0 = (j - 3) * 64;
#pragma unroll
            for (int mt = 0; mt < 2; mt++) {
                int r = base + mrow + mt * 16 + g;
#pragma unroll
                for (int nt = 0; nt < 4; nt++) {
                    int col = o0 + ncol + nt * 8 + tg * 2;
                    float* c = acc[mt][nt];
                    float* p0 = pred + (size_t)r * 255 + col;
                    float* p1 = pred + (size_t)(r + 8) * 255 + col;
                    if (col < 255) { p0[0] = c[0]; p1[0] = c[2]; }
                    if (col + 1 < 255) { p0[1] = c[1]; p1[1] = c[3]; }
                }
            }
        } else if (j >= 10) {
            // child scatter -> newF (stride 64 floats: float2 aligned); inv from gmem (L1-resident)
            int ch = j - 10;
#pragma unroll
            for (int mt = 0; mt < 2; mt++) {
                int rA = mrow + mt * 16 + g;
                bool okA = (smask[rA] >> ch) & 1, okB = (smask[rA + 8] >> ch) & 1;
                int iA = okA ? __ldg(&g_inv[(size_t)(base + rA) * 8 + ch]) : 0;
                int iB = okB ? __ldg(&g_inv[(size_t)(base + rA + 8) * 8 + ch]) : 0;
#pragma unroll
                for (int nt = 0; nt < 4; nt++) {
                    int col = ncol + nt * 8 + tg * 2;
                    float* c = acc[mt][nt];
                    if (okA) *(float2*)(newF + (size_t)iA * 64 + col) = make_float2(c[0], c[1]);
                    if (okB) *(float2*)(newF + (size_t)iB * 64 + col) = make_float2(c[2], c[3]);
                }
            }
        } else {
            // activation job: split-store to dst region (j1,j8 -> R0 else R1)
            bool dR0 = (j == 1) | (j == 8);
            char* dH = smem + (dR0 ? SM_A0H : SM_A1H);
            char* dL = dH + 18432;
#pragma unroll
            for (int mt = 0; mt < 2; mt++) {
                int r = mrow + mt * 16 + g;
#pragma unroll
                for (int nt = 0; nt < 4; nt++) {
                    uint32_t off0 = r * ARS + (ncol + nt * 8 + tg * 2) * 2;
                    uint32_t off1 = off0 + 8 * ARS;
                    float* c = acc[mt][nt];
                    __nv_bfloat16 h0, h1, h2, h3, l0, l1, l2, l3;
                    spl(c[0], h0, l0); spl(c[1], h1, l1);
                    spl(c[2], h2, l2); spl(c[3], h3, l3);
                    *(uint32_t*)(dH + off0) = pkbf(h0, h1);
                    *(uint32_t*)(dL + off0) = pkbf(l0, l1);
                    *(uint32_t*)(dH + off1) = pkbf(h2, h3);
                    *(uint32_t*)(dL + off1) = pkbf(l2, l3);
                }
            }
        }

        if (j + 1 < NJOBS) __syncthreads();   // single barrier: activation RAW + W buf visibility/WAR
    }
}

extern "C" void kernel_launch(void* const* d_in, const int* in_sizes, int n_in,
                              void* d_out, int out_size) {
    const float* X   = (const float*)d_in[0];
    const int*   bin = (const int*)d_in[1];
    const int*   sel = (const int*)d_in[2];
    const float* Wd1 = (const float*)d_in[3];
    const float* bd1 = (const float*)d_in[4];
    const float* ad  = (const float*)d_in[5];
    const float* Wd2 = (const float*)d_in[6];
    const float* bd2 = (const float*)d_in[7];
    const float* Wp1 = (const float*)d_in[8];
    const float* bp1 = (const float*)d_in[9];
    const float* ap  = (const float*)d_in[10];
    const float* Wp2 = (const float*)d_in[11];
    const float* bp2 = (const float*)d_in[12];
    const float* Wu1 = (const float*)d_in[13];
    const float* bu1 = (const float*)d_in[14];
    const float* au1 = (const float*)d_in[15];
    const float* Wu2 = (const float*)d_in[16];
    const float* bu2 = (const float*)d_in[17];
    const float* au2 = (const float*)d_in[18];
    const float* Wu3 = (const float*)d_in[19];
    const float* bu3 = (const float*)d_in[20];
    const float* Wu4 = (const float*)d_in[21];
    const float* bu4 = (const float*)d_in[22];

    int n = in_sizes[0] / 64;
    int M = in_sizes[2];
    float* newF = (float*)d_out;
    float* pred = newF + (size_t)M * 64;
    float* oct  = pred + (size_t)n * 255;

    cudaFuncSetAttribute(k_main, cudaFuncAttributeMaxDynamicSharedMemorySize, SM_TOTAL);

    k_prep<<<NJOBS, 256>>>(Wd1, Wd2, Wp1, Wp2, Wu1, Wu2, Wu3, Wu4,
                           bd1, bd2, bp1, bp2, bu1, bu2, bu3, bu4,
                           ad, ap, au1, au2);
    if (M > 0) k0_inv<<<(M + 255) / 256, 256>>>(sel, M);
    k_main<<<n / TILEM, NTHR, SM_TOTAL>>>(X, bin, Wu1, pred, oct, newF);
}

// round 9
// speedup vs baseline: 1.4410x; 1.1588x over previous
#include <cuda_runtime.h>
#include <cuda_bf16.h>
#include <cuda_fp16.h>
#include <cstdint>

#define TILEM 128
#define NTHR  256
#define NJOBS 18
#define ARS   144      // smem row stride (bytes)

// smem byte offsets
#define SM_A0H   0
#define SM_A0L   18432
#define SM_A1H   36864
#define SM_A1L   55296
#define SM_WH    73728
#define SM_WL    82944
#define SM_WTAIL 92160
#define SM_SB    94208
#define SM_SA    94464
#define SM_MASK  94720
#define SM_INV   95232
#define SM_TOTAL 99328

#define IS_HEAVY(j) (((j) >= 3 && (j) <= 6) || (j) >= 10)

// pre-split weights, [job][n][k] 64x64, 16-bit (bf16 for chain jobs, fp16 for heavy jobs)
__device__ __align__(16) unsigned short g_wh[NJOBS * 4096];
__device__ __align__(16) unsigned short g_wl[NJOBS * 4096];
__device__ int g_inv[(size_t)262144 * 8];

static __device__ __forceinline__ uint32_t smem_u32(const void* p) {
    uint32_t a;
    asm("{ .reg .u64 t; cvta.to.shared.u64 t, %1; cvt.u32.u64 %0, t; }" : "=r"(a) : "l"(p));
    return a;
}
static __device__ __forceinline__ uint32_t pkbf(__nv_bfloat16 a, __nv_bfloat16 b) {
    uint16_t ua = *(uint16_t*)&a, ub = *(uint16_t*)&b;
    return (uint32_t)ua | ((uint32_t)ub << 16);
}
static __device__ __forceinline__ float upk_lo(uint32_t u) {
    uint16_t t = (uint16_t)u; __nv_bfloat16 b = *(__nv_bfloat16*)&t; return __bfloat162float(b);
}
static __device__ __forceinline__ float upk_hi(uint32_t u) {
    uint16_t t = (uint16_t)(u >> 16); __nv_bfloat16 b = *(__nv_bfloat16*)&t; return __bfloat162float(b);
}
static __device__ __forceinline__ void spl(float v, __nv_bfloat16& h, __nv_bfloat16& l) {
    h = __float2bfloat16(v);
    l = __float2bfloat16(v - __bfloat162float(h));
}
static __device__ __forceinline__ void spl_bf_bits(float v, unsigned short& h, unsigned short& l) {
    __nv_bfloat16 hh = __float2bfloat16(v);
    __nv_bfloat16 ll = __float2bfloat16(v - __bfloat162float(hh));
    h = *(unsigned short*)&hh; l = *(unsigned short*)&ll;
}
static __device__ __forceinline__ void spl_fp16_bits(float v, unsigned short& h, unsigned short& l) {
    __half hh = __float2half(v);
    __half ll = __float2half(v - __half2float(hh));
    h = *(unsigned short*)&hh; l = *(unsigned short*)&ll;
}
static __device__ __forceinline__ uint32_t pk_half2(float a, float b) {
    __half2 t = __floats2half2_rn(a, b);
    return *(uint32_t*)&t;
}
static __device__ __forceinline__ void mma_bf16(float* c, const uint32_t* a, const uint32_t* b) {
    asm volatile(
        "mma.sync.aligned.m16n8k16.row.col.f32.bf16.bf16.f32 "
        "{%0,%1,%2,%3}, {%4,%5,%6,%7}, {%8,%9}, {%0,%1,%2,%3};"
        : "+f"(c[0]), "+f"(c[1]), "+f"(c[2]), "+f"(c[3])
        : "r"(a[0]), "r"(a[1]), "r"(a[2]), "r"(a[3]), "r"(b[0]), "r"(b[1]));
}
static __device__ __forceinline__ void mma_f16(float* c, const uint32_t* a, const uint32_t* b) {
    asm volatile(
        "mma.sync.aligned.m16n8k16.row.col.f32.f16.f16.f32 "
        "{%0,%1,%2,%3}, {%4,%5,%6,%7}, {%8,%9}, {%0,%1,%2,%3};"
        : "+f"(c[0]), "+f"(c[1]), "+f"(c[2]), "+f"(c[3])
        : "r"(a[0]), "r"(a[1]), "r"(a[2]), "r"(a[3]), "r"(b[0]), "r"(b[1]));
}
static __device__ __forceinline__ void ldm4(uint32_t* r, uint32_t addr) {
    asm volatile("ldmatrix.sync.aligned.m8n8.x4.shared.b16 {%0,%1,%2,%3}, [%4];"
        : "=r"(r[0]), "=r"(r[1]), "=r"(r[2]), "=r"(r[3]) : "r"(addr));
}

// ---------------- K_prep: split weights (bf16 chain / fp16 heavy), [n][k] layout ----------------
__global__ void k_prep(const float* __restrict__ Wd1, const float* __restrict__ Wd2,
                       const float* __restrict__ Wp1, const float* __restrict__ Wp2,
                       const float* __restrict__ Wu1, const float* __restrict__ Wu2,
                       const float* __restrict__ Wu3, const float* __restrict__ Wu4) {
    int j = blockIdx.x;
    bool heavy = IS_HEAVY(j);
    for (int t = threadIdx.x; t < 4096; t += 256) {
        int n = t >> 6, k = t & 63;
        float v;
        if (j == 0)      v = Wd1[k * 64 + n];
        else if (j == 1) v = Wd2[k * 64 + n];
        else if (j == 2) v = Wp1[k * 64 + n];
        else if (j <= 6) { int ng = (j - 3) * 64 + n; v = (ng < 255) ? Wp2[k * 255 + ng] : 0.f; }
        else if (j == 7) v = Wu1[k * 64 + n];
        else if (j == 8) v = Wu2[k * 64 + n];
        else if (j == 9) v = Wu3[k * 64 + n];
        else             v = Wu4[(size_t)k * 512 + (j - 10) * 64 + n];
        unsigned short h, l;
        if (heavy) spl_fp16_bits(v, h, l);
        else       spl_bf_bits(v, h, l);
        g_wh[j * 4096 + t] = h;
        g_wl[j * 4096 + t] = l;
    }
}

// ---------------- K0: inverse map of sel_idx ----------------
__global__ void k0_inv(const int* __restrict__ sel, int M) {
    int m = blockIdx.x * 256 + threadIdx.x;
    if (m < M) g_inv[sel[m]] = m;
}

// ---------------- fused main kernel ----------------
__global__ __launch_bounds__(NTHR, 2)
void k_main(const float* __restrict__ X, const int* __restrict__ bin,
            const float* __restrict__ bd1, const float* __restrict__ ad,
            const float* __restrict__ bd2,
            const float* __restrict__ bp1, const float* __restrict__ ap_,
            const float* __restrict__ bp2,
            const float* __restrict__ bu1, const float* __restrict__ au1,
            const float* __restrict__ bu2, const float* __restrict__ au2,
            const float* __restrict__ bu3, const float* __restrict__ bu4,
            const float* __restrict__ Wu1,
            float* __restrict__ pred, float* __restrict__ oct, float* __restrict__ newF) {
    extern __shared__ char smem[];
    const uint32_t sb = smem_u32(smem);
    int tid = threadIdx.x;
    int wid = tid >> 5, lane = tid & 31;
    int g = lane >> 2, tg = lane & 3;
    int mrow = (wid >> 1) * 32;       // 4 m-quarters
    int ncol = (wid & 1) * 32;        // 2 n-halves
    int base = blockIdx.x * TILEM;

    float* sB    = (float*)(smem + SM_SB);
    float* sA    = (float*)(smem + SM_SA);
    float* wtail = (float*)(smem + SM_WTAIL);
    int*   smask = (int*)(smem + SM_MASK);
    int*   sinv  = (int*)(smem + SM_INV);

    // ---- prologue: X -> R0 (split bf16), mask/inv/oct, Wu1 tail ----
    {
        const float4* Xr = (const float4*)(X + (size_t)base * 64);
#pragma unroll
        for (int it = 0; it < 8; it++) {
            int idx = it * NTHR + tid;            // 0..2047 float4s
            int row = idx >> 4, q = idx & 15;
            float4 v = Xr[idx];
            __nv_bfloat16 h0, h1, h2, h3, l0, l1, l2, l3;
            spl(v.x, h0, l0); spl(v.y, h1, l1); spl(v.z, h2, l2); spl(v.w, h3, l3);
            *(uint2*)(smem + SM_A0H + row * ARS + q * 8) = make_uint2(pkbf(h0, h1), pkbf(h2, h3));
            *(uint2*)(smem + SM_A0L + row * ARS + q * 8) = make_uint2(pkbf(l0, l1), pkbf(l2, l3));
        }
        if (tid < TILEM) {
            const int* bp = bin + (size_t)(base + tid) * 8;
            int4 b0 = *(const int4*)bp;
            int4 b1 = *(const int4*)(bp + 4);
            int m = (b0.x != 0) | ((b0.y != 0) << 1) | ((b0.z != 0) << 2) | ((b0.w != 0) << 3)
                  | ((b1.x != 0) << 4) | ((b1.y != 0) << 5) | ((b1.z != 0) << 6) | ((b1.w != 0) << 7);
            smask[tid] = m;
            oct[base + tid] = (float)(m - 1);
            const int* ip = g_inv + (size_t)(base + tid) * 8;
            int4 i0 = *(const int4*)ip;
            int4 i1 = *(const int4*)(ip + 4);
            *(int4*)(sinv + tid * 8)     = i0;
            *(int4*)(sinv + tid * 8 + 4) = i1;
        }
#pragma unroll
        for (int it = 0; it < 2; it++)
            wtail[it * NTHR + tid] = Wu1[4096 + it * NTHR + tid];
    }

    // ---- weight/bias register prefetch (job 0) ----
    uint4 wr0, wr1, wr2, wr3;
    float bn = 0.f, an = 0.25f;
    {
        const uint4* sh = (const uint4*)(g_wh);
        const uint4* sl = (const uint4*)(g_wl);
        wr0 = sh[tid]; wr1 = sh[tid + 256];
        wr2 = sl[tid]; wr3 = sl[tid + 256];
        if (tid < 64) { bn = bd1[tid]; an = ad[tid]; }
    }

    // ldmatrix lane base offsets
    uint32_t aoff = (uint32_t)((mrow + (lane & 7) + ((lane >> 3) & 1) * 8) * ARS
                              + ((lane >> 4) & 1) * 16);
    uint32_t woff = (uint32_t)((ncol + (lane & 7) + ((lane >> 4) & 1) * 8) * ARS
                              + ((lane >> 3) & 1) * 16);
    uint32_t wHb = sb + SM_WH + woff;
    uint32_t wLb = sb + SM_WL + woff;

    for (int j = 0; j < NJOBS; j++) {
        __syncthreads();   // prior GEMM/epilogue complete
        // ---- commit prefetched W + bias to smem ----
        {
            int i0 = tid, i1 = tid + 256;
            *(uint4*)(smem + SM_WH + (i0 >> 3) * ARS + (i0 & 7) * 16) = wr0;
            *(uint4*)(smem + SM_WH + (i1 >> 3) * ARS + (i1 & 7) * 16) = wr1;
            *(uint4*)(smem + SM_WL + (i0 >> 3) * ARS + (i0 & 7) * 16) = wr2;
            *(uint4*)(smem + SM_WL + (i1 >> 3) * ARS + (i1 & 7) * 16) = wr3;
            if (tid < 64) { sB[tid] = bn; sA[tid] = an; }
        }
        __syncthreads();

        // ---- prefetch next job's W + bias into registers (hidden by GEMM) ----
        if (j + 1 < NJOBS) {
            int jn = j + 1;
            const uint4* sh = (const uint4*)(g_wh + jn * 4096);
            const uint4* sl = (const uint4*)(g_wl + jn * 4096);
            wr0 = sh[tid]; wr1 = sh[tid + 256];
            wr2 = sl[tid]; wr3 = sl[tid + 256];
            if (tid < 64) {
                int c = tid; float b = 0.f, a = 0.25f;
                switch (jn) {
                    case 1: b = bd2[c]; break;
                    case 2: b = bp1[c]; a = ap_[c]; break;
                    case 3: case 4: case 5: case 6: {
                        int ng = (jn - 3) * 64 + c; b = (ng < 255) ? bp2[ng] : 0.f; break; }
                    case 7: b = bu1[c]; a = au1[c]; break;
                    case 8: b = bu2[c]; a = au2[c]; break;
                    case 9: b = bu3[c]; break;
                    default: b = bu4[(jn - 10) * 64 + c]; break;
                }
                bn = b; an = a;
            }
        }

        // ---- GEMM; warp tile m32 x n32 ----
        bool heavy = IS_HEAVY(j);
        bool aR0 = (j == 0) | (j == 2) | (j == 7) | (j == 9);
        uint32_t aHb = sb + (aR0 ? SM_A0H : SM_A1H) + aoff;
        uint32_t aLb = aHb + 18432;

        float acc[2][4][4];
#pragma unroll
        for (int mt = 0; mt < 2; mt++)
#pragma unroll
            for (int nt = 0; nt < 4; nt++)
#pragma unroll
                for (int i = 0; i < 4; i++) acc[mt][nt][i] = 0.f;

        if (heavy) {
            // A single fp16, B 2-term fp16: c += a*Wh + a*Wl
#pragma unroll
            for (int kc = 0; kc < 4; kc++) {
                uint32_t ko = kc * 32;
                uint32_t a2[2][4], bh[2][4], bl[2][4];
                ldm4(a2[0], aHb + ko); ldm4(a2[1], aHb + ko + 16 * ARS);
                ldm4(bh[0], wHb + ko); ldm4(bh[1], wHb + ko + 16 * ARS);
                ldm4(bl[0], wLb + ko); ldm4(bl[1], wLb + ko + 16 * ARS);
#pragma unroll
                for (int p2 = 0; p2 < 2; p2++)
#pragma unroll
                    for (int h = 0; h < 2; h++) {
                        int nt = p2 * 2 + h;
                        const uint32_t* Bh = &bh[p2][h * 2];
                        const uint32_t* Bl = &bl[p2][h * 2];
#pragma unroll
                        for (int mt = 0; mt < 2; mt++) {
                            float* c = acc[mt][nt];
                            mma_f16(c, a2[mt], Bh);
                            mma_f16(c, a2[mt], Bl);
                        }
                    }
            }
        } else {
            // 3-term bf16 split: c += Ah*Bh + Ah*Bl + Al*Bh
#pragma unroll
            for (int kc = 0; kc < 4; kc++) {
                uint32_t ko = kc * 32;
                uint32_t ah[2][4], al[2][4], bh[2][4], bl[2][4];
                ldm4(ah[0], aHb + ko); ldm4(ah[1], aHb + ko + 16 * ARS);
                ldm4(al[0], aLb + ko); ldm4(al[1], aLb + ko + 16 * ARS);
                ldm4(bh[0], wHb + ko); ldm4(bh[1], wHb + ko + 16 * ARS);
                ldm4(bl[0], wLb + ko); ldm4(bl[1], wLb + ko + 16 * ARS);
#pragma unroll
                for (int p2 = 0; p2 < 2; p2++)
#pragma unroll
                    for (int h = 0; h < 2; h++) {
                        int nt = p2 * 2 + h;
                        const uint32_t* Bh = &bh[p2][h * 2];
                        const uint32_t* Bl = &bl[p2][h * 2];
#pragma unroll
                        for (int mt = 0; mt < 2; mt++) {
                            float* c = acc[mt][nt];
                            mma_bf16(c, ah[mt], Bh);
                            mma_bf16(c, ah[mt], Bl);
                            mma_bf16(c, al[mt], Bh);
                        }
                    }
            }
        }

        // ---- epilogue ----
#pragma unroll
        for (int nt = 0; nt < 4; nt++) {
            int col = ncol + nt * 8 + tg * 2;
            float2 bb = *(const float2*)(sB + col);
#pragma unroll
            for (int mt = 0; mt < 2; mt++) {
                float* c = acc[mt][nt];
                c[0] += bb.x; c[1] += bb.y; c[2] += bb.x; c[3] += bb.y;
            }
        }

        if (j == 7) {   // bin-concat tail: + 256 * Wu1[64+jj][col] for set bits (exact)
#pragma unroll
            for (int mt = 0; mt < 2; mt++) {
                int rA = mrow + mt * 16 + g;
                int mA = smask[rA], mB = smask[rA + 8];
#pragma unroll
                for (int jj = 0; jj < 8; jj++) {
                    bool bA = (mA >> jj) & 1, bB = (mB >> jj) & 1;
                    if (bA | bB) {
#pragma unroll
                        for (int nt = 0; nt < 4; nt++) {
                            float2 t = *(const float2*)(wtail + jj * 64 + ncol + nt * 8 + tg * 2);
                            float* c = acc[mt][nt];
                            if (bA) { c[0] += 256.f * t.x; c[1] += 256.f * t.y; }
                            if (bB) { c[2] += 256.f * t.x; c[3] += 256.f * t.y; }
                        }
                    }
                }
            }
        }
        if (j == 0 || j == 2 || j == 7 || j == 8) {  // prelu
#pragma unroll
            for (int nt = 0; nt < 4; nt++) {
                int col = ncol + nt * 8 + tg * 2;
                float2 aa = *(const float2*)(sA + col);
#pragma unroll
                for (int mt = 0; mt < 2; mt++) {
                    float* c = acc[mt][nt];
                    c[0] = c[0] >= 0.f ? c[0] : aa.x * c[0];
                    c[1] = c[1] >= 0.f ? c[1] : aa.y * c[1];
                    c[2] = c[2] >= 0.f ? c[2] : aa.x * c[2];
                    c[3] = c[3] >= 0.f ? c[3] : aa.y * c[3];
                }
            }
        }
        if (j == 1 || j == 9) {  // residual (j1: +X in R0; j9: +u1 in R1)
            const char* rH = smem + (j == 1 ? SM_A0H : SM_A1H);
            const char* rL = rH + 18432;
#pragma unroll
            for (int mt = 0; mt < 2; mt++) {
                int r = mrow + mt * 16 + g;
#pragma unroll
                for (int nt = 0; nt < 4; nt++) {
                    uint32_t off0 = r * ARS + (ncol + nt * 8 + tg * 2) * 2;
                    uint32_t off1 = off0 + 8 * ARS;
                    uint32_t h0 = *(const uint32_t*)(rH + off0), l0 = *(const uint32_t*)(rL + off0);
                    uint32_t h1 = *(const uint32_t*)(rH + off1), l1 = *(const uint32_t*)(rL + off1);
                    float* c = acc[mt][nt];
                    c[0] += upk_lo(h0) + upk_lo(l0);
                    c[1] += upk_hi(h0) + upk_hi(l0);
                    c[2] += upk_lo(h1) + upk_lo(l1);
                    c[3] += upk_hi(h1) + upk_hi(l1);
                }
            }
        }

        if (j >= 3 && j <= 6) {
            // pred -> gmem; stride 255 floats is odd -> scalar 4B stores
            int o0 = (j - 3) * 64;
#pragma unroll
            for (int mt = 0; mt < 2; mt++) {
                int r = base + mrow + mt * 16 + g;
#pragma unroll
                for (int nt = 0; nt < 4; nt++) {
                    int col = o0 + ncol + nt * 8 + tg * 2;
                    float* c = acc[mt][nt];
                    float* p0 = pred + (size_t)r * 255 + col;
                    float* p1 = pred + (size_t)(r + 8) * 255 + col;
                    if (col < 255) { p0[0] = c[0]; p1[0] = c[2]; }
                    if (col + 1 < 255) { p0[1] = c[1]; p1[1] = c[3]; }
                }
            }
        } else if (j >= 10) {
            // child scatter -> newF (stride 64 floats: float2 aligned)
            int ch = j - 10;
#pragma unroll
            for (int mt = 0; mt < 2; mt++) {
                int rA = mrow + mt * 16 + g;
                bool okA = (smask[rA] >> ch) & 1, okB = (smask[rA + 8] >> ch) & 1;
                int iA = sinv[rA * 8 + ch], iB = sinv[(rA + 8) * 8 + ch];
#pragma unroll
                for (int nt = 0; nt < 4; nt++) {
                    int col = ncol + nt * 8 + tg * 2;
                    float* c = acc[mt][nt];
                    if (okA) *(float2*)(newF + (size_t)iA * 64 + col) = make_float2(c[0], c[1]);
                    if (okB) *(float2*)(newF + (size_t)iB * 64 + col) = make_float2(c[2], c[3]);
                }
            }
        } else if (j == 2 || j == 9) {
            // p / u -> R1, SINGLE fp16 (consumed only by heavy fp16 jobs)
            char* dH = smem + SM_A1H;
#pragma unroll
            for (int mt = 0; mt < 2; mt++) {
                int r = mrow + mt * 16 + g;
#pragma unroll
                for (int nt = 0; nt < 4; nt++) {
                    uint32_t off0 = r * ARS + (ncol + nt * 8 + tg * 2) * 2;
                    uint32_t off1 = off0 + 8 * ARS;
                    float* c = acc[mt][nt];
                    *(uint32_t*)(dH + off0) = pk_half2(c[0], c[1]);
                    *(uint32_t*)(dH + off1) = pk_half2(c[2], c[3]);
                }
            }
        } else {
            // chain activation: split-store bf16 hi/lo (j1,j8 -> R0 else R1)
            bool dR0 = (j == 1) | (j == 8);
            char* dH = smem + (dR0 ? SM_A0H : SM_A1H);
            char* dL = dH + 18432;
#pragma unroll
            for (int mt = 0; mt < 2; mt++) {
                int r = mrow + mt * 16 + g;
#pragma unroll
                for (int nt = 0; nt < 4; nt++) {
                    uint32_t off0 = r * ARS + (ncol + nt * 8 + tg * 2) * 2;
                    uint32_t off1 = off0 + 8 * ARS;
                    float* c = acc[mt][nt];
                    __nv_bfloat16 h0, h1, h2, h3, l0, l1, l2, l3;
                    spl(c[0], h0, l0); spl(c[1], h1, l1);
                    spl(c[2], h2, l2); spl(c[3], h3, l3);
                    *(uint32_t*)(dH + off0) = pkbf(h0, h1);
                    *(uint32_t*)(dL + off0) = pkbf(l0, l1);
                    *(uint32_t*)(dH + off1) = pkbf(h2, h3);
                    *(uint32_t*)(dL + off1) = pkbf(l2, l3);
                }
            }
        }
    }
}

extern "C" void kernel_launch(void* const* d_in, const int* in_sizes, int n_in,
                              void* d_out, int out_size) {
    const float* X   = (const float*)d_in[0];
    const int*   bin = (const int*)d_in[1];
    const int*   sel = (const int*)d_in[2];
    const float* Wd1 = (const float*)d_in[3];
    const float* bd1 = (const float*)d_in[4];
    const float* ad  = (const float*)d_in[5];
    const float* Wd2 = (const float*)d_in[6];
    const float* bd2 = (const float*)d_in[7];
    const float* Wp1 = (const float*)d_in[8];
    const float* bp1 = (const float*)d_in[9];
    const float* ap  = (const float*)d_in[10];
    const float* Wp2 = (const float*)d_in[11];
    const float* bp2 = (const float*)d_in[12];
    const float* Wu1 = (const float*)d_in[13];
    const float* bu1 = (const float*)d_in[14];
    const float* au1 = (const float*)d_in[15];
    const float* Wu2 = (const float*)d_in[16];
    const float* bu2 = (const float*)d_in[17];
    const float* au2 = (const float*)d_in[18];
    const float* Wu3 = (const float*)d_in[19];
    const float* bu3 = (const float*)d_in[20];
    const float* Wu4 = (const float*)d_in[21];
    const float* bu4 = (const float*)d_in[22];

    int n = in_sizes[0] / 64;
    int M = in_sizes[2];
    float* newF = (float*)d_out;
    float* pred = newF + (size_t)M * 64;
    float* oct  = pred + (size_t)n * 255;

    cudaFuncSetAttribute(k_main, cudaFuncAttributeMaxDynamicSharedMemorySize, SM_TOTAL);

    k_prep<<<NJOBS, 256>>>(Wd1, Wd2, Wp1, Wp2, Wu1, Wu2, Wu3, Wu4);
    if (M > 0) k0_inv<<<(M + 255) / 256, 256>>>(sel, M);
    k_main<<<n / TILEM, NTHR, SM_TOTAL>>>(X, bin, bd1, ad, bd2, bp1, ap, bp2,
                                          bu1, au1, bu2, au2, bu3, bu4, Wu1,
                                          pred, oct, newF);
}

// round 10
// speedup vs baseline: 1.7040x; 1.1825x over previous
#include <cuda_runtime.h>
#include <cuda_bf16.h>
#include <cuda_fp16.h>
#include <cstdint>

#define TILEM 128
#define NTHR  256
#define ARS   144      // smem row stride (bytes)

// smem byte offsets
#define SM_R0H   0
#define SM_R0L   18432
#define SM_R1H   36864
#define SM_R1L   55296
#define SM_WH    73728
#define SM_WL    82944
#define SM_WTAIL 92160
#define SM_MASK  94208
#define SM_SINV  94720
#define SM_TOTAL 98816

// chain weights (bf16 hi/lo, [n][k] 64x64), slots: 0=Wd1 1=Wd2 2=Wp1 3=Wu1 4=Wu2 5=Wu3
__device__ __align__(16) __nv_bfloat16 g_wh[6 * 4096];
__device__ __align__(16) __nv_bfloat16 g_wl[6 * 4096];
// heavy weights (fp16 single, [n][k] 64x64), chunks: 0-3 = Wp2, 4-11 = Wu4
__device__ __align__(16) __half g_wx[12 * 4096];
__device__ __align__(16) float g_bb[18 * 64];
__device__ __align__(16) float g_aw[18 * 64];
__device__ int g_inv[(size_t)262144 * 8];

static __device__ __forceinline__ uint32_t smem_u32(const void* p) {
    uint32_t a;
    asm("{ .reg .u64 t; cvta.to.shared.u64 t, %1; cvt.u32.u64 %0, t; }" : "=r"(a) : "l"(p));
    return a;
}
static __device__ __forceinline__ uint32_t pkbf(__nv_bfloat16 a, __nv_bfloat16 b) {
    uint16_t ua = *(uint16_t*)&a, ub = *(uint16_t*)&b;
    return (uint32_t)ua | ((uint32_t)ub << 16);
}
static __device__ __forceinline__ float upk_lo(uint32_t u) {
    uint16_t t = (uint16_t)u; __nv_bfloat16 b = *(__nv_bfloat16*)&t; return __bfloat162float(b);
}
static __device__ __forceinline__ float upk_hi(uint32_t u) {
    uint16_t t = (uint16_t)(u >> 16); __nv_bfloat16 b = *(__nv_bfloat16*)&t; return __bfloat162float(b);
}
static __device__ __forceinline__ void spl(float v, __nv_bfloat16& h, __nv_bfloat16& l) {
    h = __float2bfloat16(v);
    l = __float2bfloat16(v - __bfloat162float(h));
}
static __device__ __forceinline__ uint32_t pk_half2(float a, float b) {
    __half2 t = __floats2half2_rn(a, b);
    return *(uint32_t*)&t;
}
static __device__ __forceinline__ void mma_bf16(float* c, const uint32_t* a, const uint32_t* b) {
    asm volatile(
        "mma.sync.aligned.m16n8k16.row.col.f32.bf16.bf16.f32 "
        "{%0,%1,%2,%3}, {%4,%5,%6,%7}, {%8,%9}, {%0,%1,%2,%3};"
        : "+f"(c[0]), "+f"(c[1]), "+f"(c[2]), "+f"(c[3])
        : "r"(a[0]), "r"(a[1]), "r"(a[2]), "r"(a[3]), "r"(b[0]), "r"(b[1]));
}
static __device__ __forceinline__ void mma_f16(float* c, const uint32_t* a, const uint32_t* b) {
    asm volatile(
        "mma.sync.aligned.m16n8k16.row.col.f32.f16.f16.f32 "
        "{%0,%1,%2,%3}, {%4,%5,%6,%7}, {%8,%9}, {%0,%1,%2,%3};"
        : "+f"(c[0]), "+f"(c[1]), "+f"(c[2]), "+f"(c[3])
        : "r"(a[0]), "r"(a[1]), "r"(a[2]), "r"(a[3]), "r"(b[0]), "r"(b[1]));
}
static __device__ __forceinline__ void ldm4(uint32_t* r, uint32_t addr) {
    asm volatile("ldmatrix.sync.aligned.m8n8.x4.shared.b16 {%0,%1,%2,%3}, [%4];"
        : "=r"(r[0]), "=r"(r[1]), "=r"(r[2]), "=r"(r[3]) : "r"(addr));
}
static __device__ __forceinline__ void zero_acc(float acc[2][4][4]) {
#pragma unroll
    for (int mt = 0; mt < 2; mt++)
#pragma unroll
        for (int nt = 0; nt < 4; nt++)
#pragma unroll
            for (int i = 0; i < 4; i++) acc[mt][nt][i] = 0.f;
}

// 3-term bf16-split chain GEMM; warp tile m32 x n32
static __device__ __forceinline__ void chain_gemm(uint32_t aHb, uint32_t wHb, uint32_t wLb,
                                                  float acc[2][4][4]) {
    uint32_t aLb = aHb + 18432;
#pragma unroll
    for (int kc = 0; kc < 4; kc++) {
        uint32_t ko = kc * 32;
        uint32_t ah[2][4], al[2][4], bh[2][4], bl[2][4];
        ldm4(ah[0], aHb + ko); ldm4(ah[1], aHb + ko + 16 * ARS);
        ldm4(al[0], aLb + ko); ldm4(al[1], aLb + ko + 16 * ARS);
        ldm4(bh[0], wHb + ko); ldm4(bh[1], wHb + ko + 16 * ARS);
        ldm4(bl[0], wLb + ko); ldm4(bl[1], wLb + ko + 16 * ARS);
#pragma unroll
        for (int p2 = 0; p2 < 2; p2++)
#pragma unroll
            for (int h = 0; h < 2; h++) {
                int nt = p2 * 2 + h;
                const uint32_t* Bh = &bh[p2][h * 2];
                const uint32_t* Bl = &bl[p2][h * 2];
#pragma unroll
                for (int mt = 0; mt < 2; mt++) {
                    float* c = acc[mt][nt];
                    mma_bf16(c, ah[mt], Bh);
                    mma_bf16(c, ah[mt], Bl);
                    mma_bf16(c, al[mt], Bh);
                }
            }
    }
}

// single-term fp16 heavy GEMM with register-cached A
static __device__ __forceinline__ void heavy_gemm(const uint32_t aC[4][2][4], uint32_t wb,
                                                  float acc[2][4][4]) {
#pragma unroll
    for (int kc = 0; kc < 4; kc++) {
        uint32_t ko = kc * 32;
        uint32_t bh[2][4];
        ldm4(bh[0], wb + ko); ldm4(bh[1], wb + ko + 16 * ARS);
#pragma unroll
        for (int p2 = 0; p2 < 2; p2++)
#pragma unroll
            for (int h = 0; h < 2; h++) {
                int nt = p2 * 2 + h;
                const uint32_t* Bh = &bh[p2][h * 2];
#pragma unroll
                for (int mt = 0; mt < 2; mt++)
                    mma_f16(acc[mt][nt], aC[kc][mt], Bh);
            }
    }
}

static __device__ __forceinline__ void add_bias(float acc[2][4][4], int j, int ncol, int tg) {
    const float* bb = g_bb + j * 64;
#pragma unroll
    for (int nt = 0; nt < 4; nt++) {
        float2 bv = __ldg((const float2*)(bb + ncol + nt * 8 + tg * 2));
#pragma unroll
        for (int mt = 0; mt < 2; mt++) {
            float* c = acc[mt][nt];
            c[0] += bv.x; c[1] += bv.y; c[2] += bv.x; c[3] += bv.y;
        }
    }
}
static __device__ __forceinline__ void apply_prelu(float acc[2][4][4], int j, int ncol, int tg) {
    const float* aw = g_aw + j * 64;
#pragma unroll
    for (int nt = 0; nt < 4; nt++) {
        float2 av = __ldg((const float2*)(aw + ncol + nt * 8 + tg * 2));
#pragma unroll
        for (int mt = 0; mt < 2; mt++) {
            float* c = acc[mt][nt];
            c[0] = c[0] >= 0.f ? c[0] : av.x * c[0];
            c[1] = c[1] >= 0.f ? c[1] : av.y * c[1];
            c[2] = c[2] >= 0.f ? c[2] : av.x * c[2];
            c[3] = c[3] >= 0.f ? c[3] : av.y * c[3];
        }
    }
}
// += hi+lo bf16 pair read from region rH (lo at +18432)
static __device__ __forceinline__ void add_residual(const char* rH, float acc[2][4][4],
                                                    int mrow, int g, int ncol, int tg) {
    const char* rL = rH + 18432;
#pragma unroll
    for (int mt = 0; mt < 2; mt++) {
        int r = mrow + mt * 16 + g;
#pragma unroll
        for (int nt = 0; nt < 4; nt++) {
            uint32_t off0 = r * ARS + (ncol + nt * 8 + tg * 2) * 2;
            uint32_t off1 = off0 + 8 * ARS;
            uint32_t h0 = *(const uint32_t*)(rH + off0), l0 = *(const uint32_t*)(rL + off0);
            uint32_t h1 = *(const uint32_t*)(rH + off1), l1 = *(const uint32_t*)(rL + off1);
            float* c = acc[mt][nt];
            c[0] += upk_lo(h0) + upk_lo(l0);
            c[1] += upk_hi(h0) + upk_hi(l0);
            c[2] += upk_lo(h1) + upk_lo(l1);
            c[3] += upk_hi(h1) + upk_hi(l1);
        }
    }
}
static __device__ __forceinline__ void store_bf_hilo(char* dH, float acc[2][4][4],
                                                     int mrow, int g, int ncol, int tg) {
    char* dL = dH + 18432;
#pragma unroll
    for (int mt = 0; mt < 2; mt++) {
        int r = mrow + mt * 16 + g;
#pragma unroll
        for (int nt = 0; nt < 4; nt++) {
            uint32_t off0 = r * ARS + (ncol + nt * 8 + tg * 2) * 2;
            uint32_t off1 = off0 + 8 * ARS;
            float* c = acc[mt][nt];
            __nv_bfloat16 h0, h1, h2, h3, l0, l1, l2, l3;
            spl(c[0], h0, l0); spl(c[1], h1, l1);
            spl(c[2], h2, l2); spl(c[3], h3, l3);
            *(uint32_t*)(dH + off0) = pkbf(h0, h1);
            *(uint32_t*)(dL + off0) = pkbf(l0, l1);
            *(uint32_t*)(dH + off1) = pkbf(h2, h3);
            *(uint32_t*)(dL + off1) = pkbf(l2, l3);
        }
    }
}
static __device__ __forceinline__ void store_f16(char* dH, float acc[2][4][4],
                                                 int mrow, int g, int ncol, int tg) {
#pragma unroll
    for (int mt = 0; mt < 2; mt++) {
        int r = mrow + mt * 16 + g;
#pragma unroll
        for (int nt = 0; nt < 4; nt++) {
            uint32_t off0 = r * ARS + (ncol + nt * 8 + tg * 2) * 2;
            uint32_t off1 = off0 + 8 * ARS;
            float* c = acc[mt][nt];
            *(uint32_t*)(dH + off0) = pk_half2(c[0], c[1]);
            *(uint32_t*)(dH + off1) = pk_half2(c[2], c[3]);
        }
    }
}

// ---------------- K_prep ----------------
__global__ void k_prep(const float* __restrict__ Wd1, const float* __restrict__ Wd2,
                       const float* __restrict__ Wp1, const float* __restrict__ Wp2,
                       const float* __restrict__ Wu1, const float* __restrict__ Wu2,
                       const float* __restrict__ Wu3, const float* __restrict__ Wu4,
                       const float* __restrict__ bd1, const float* __restrict__ bd2,
                       const float* __restrict__ bp1, const float* __restrict__ bp2,
                       const float* __restrict__ bu1, const float* __restrict__ bu2,
                       const float* __restrict__ bu3, const float* __restrict__ bu4,
                       const float* __restrict__ ad,  const float* __restrict__ ap_,
                       const float* __restrict__ au1, const float* __restrict__ au2) {
    int j = blockIdx.x;
    int slot = (j == 0) ? 0 : (j == 1) ? 1 : (j == 2) ? 2 :
               (j == 7) ? 3 : (j == 8) ? 4 : (j == 9) ? 5 : -1;
    for (int t = threadIdx.x; t < 4096; t += 256) {
        int n = t >> 6, k = t & 63;
        float v;
        if (j == 0)      v = Wd1[k * 64 + n];
        else if (j == 1) v = Wd2[k * 64 + n];
        else if (j == 2) v = Wp1[k * 64 + n];
        else if (j <= 6) { int ng = (j - 3) * 64 + n; v = (ng < 255) ? Wp2[k * 255 + ng] : 0.f; }
        else if (j == 7) v = Wu1[k * 64 + n];
        else if (j == 8) v = Wu2[k * 64 + n];
        else if (j == 9) v = Wu3[k * 64 + n];
        else             v = Wu4[(size_t)k * 512 + (j - 10) * 64 + n];
        if (slot >= 0) {
            __nv_bfloat16 h, l; spl(v, h, l);
            g_wh[slot * 4096 + t] = h;
            g_wl[slot * 4096 + t] = l;
        } else {
            int ch = (j <= 6) ? (j - 3) : (4 + j - 10);
            g_wx[ch * 4096 + n * 64 + k] = __float2half(v);
        }
    }
    int t = threadIdx.x;
    if (t < 64) {
        int c = t; float b = 0.f, a = 0.f;
        switch (j) {
            case 0: b = bd1[c]; a = ad[c]; break;
            case 1: b = bd2[c]; break;
            case 2: b = bp1[c]; a = ap_[c]; break;
            case 3: case 4: case 5: case 6: {
                int ng = (j - 3) * 64 + c; b = (ng < 255) ? bp2[ng] : 0.f; break; }
            case 7: b = bu1[c]; a = au1[c]; break;
            case 8: b = bu2[c]; a = au2[c]; break;
            case 9: b = bu3[c]; break;
            default: b = bu4[(j - 10) * 64 + c]; break;
        }
        g_bb[j * 64 + c] = b;
        g_aw[j * 64 + c] = a;
    }
}

// ---------------- K0: inverse map ----------------
__global__ void k0_inv(const int* __restrict__ sel, int M) {
    int m = blockIdx.x * 256 + threadIdx.x;
    if (m < M) g_inv[sel[m]] = m;
}

// ---------------- fused main kernel ----------------
__global__ __launch_bounds__(NTHR, 2)
void k_main(const float* __restrict__ X, const int* __restrict__ bin,
            const float* __restrict__ Wu1,
            float* __restrict__ pred, float* __restrict__ oct, float* __restrict__ newF) {
    extern __shared__ char smem[];
    const uint32_t sb = smem_u32(smem);
    int tid = threadIdx.x;
    int wid = tid >> 5, lane = tid & 31;
    int g = lane >> 2, tg = lane & 3;
    int mrow = (wid >> 1) * 32;
    int ncol = (wid & 1) * 32;
    int base = blockIdx.x * TILEM;

    float* wtail = (float*)(smem + SM_WTAIL);
    int*   smask = (int*)(smem + SM_MASK);
    int*   sinv  = (int*)(smem + SM_SINV);

    // ---- prologue: X -> R0 hi/lo, mask/oct/sinv, wtail ----
    {
        const float4* Xr = (const float4*)(X + (size_t)base * 64);
#pragma unroll
        for (int it = 0; it < 8; it++) {
            int idx = it * NTHR + tid;
            int row = idx >> 4, q = idx & 15;
            float4 v = Xr[idx];
            __nv_bfloat16 h0, h1, h2, h3, l0, l1, l2, l3;
            spl(v.x, h0, l0); spl(v.y, h1, l1); spl(v.z, h2, l2); spl(v.w, h3, l3);
            *(uint2*)(smem + SM_R0H + row * ARS + q * 8) = make_uint2(pkbf(h0, h1), pkbf(h2, h3));
            *(uint2*)(smem + SM_R0L + row * ARS + q * 8) = make_uint2(pkbf(l0, l1), pkbf(l2, l3));
        }
        if (tid < TILEM) {
            const int* bp = bin + (size_t)(base + tid) * 8;
            int4 b0 = *(const int4*)bp;
            int4 b1 = *(const int4*)(bp + 4);
            int m = (b0.x != 0) | ((b0.y != 0) << 1) | ((b0.z != 0) << 2) | ((b0.w != 0) << 3)
                  | ((b1.x != 0) << 4) | ((b1.y != 0) << 5) | ((b1.z != 0) << 6) | ((b1.w != 0) << 7);
            smask[tid] = m;
            oct[base + tid] = (float)(m - 1);
            const int* ip = g_inv + (size_t)(base + tid) * 8;
            int4 i0 = *(const int4*)ip;
            int4 i1 = *(const int4*)(ip + 4);
            *(int4*)(sinv + tid * 8)     = i0;
            *(int4*)(sinv + tid * 8 + 4) = i1;
        }
#pragma unroll
        for (int it = 0; it < 2; it++)
            wtail[it * NTHR + tid] = Wu1[4096 + it * NTHR + tid];
    }

    uint4 wr0, wr1, wr2, wr3;
    auto prefetchW = [&](int slot) {
        const uint4* sh = (const uint4*)(g_wh + slot * 4096);
        const uint4* sl = (const uint4*)(g_wl + slot * 4096);
        wr0 = sh[tid]; wr1 = sh[tid + 256];
        wr2 = sl[tid]; wr3 = sl[tid + 256];
    };
    auto commitW = [&]() {
        int i0 = tid, i1 = tid + 256;
        *(uint4*)(smem + SM_WH + (i0 >> 3) * ARS + (i0 & 7) * 16) = wr0;
        *(uint4*)(smem + SM_WH + (i1 >> 3) * ARS + (i1 & 7) * 16) = wr1;
        *(uint4*)(smem + SM_WL + (i0 >> 3) * ARS + (i0 & 7) * 16) = wr2;
        *(uint4*)(smem + SM_WL + (i1 >> 3) * ARS + (i1 & 7) * 16) = wr3;
    };

    uint32_t aoff = (uint32_t)((mrow + (lane & 7) + ((lane >> 3) & 1) * 8) * ARS
                              + ((lane >> 4) & 1) * 16);
    uint32_t woff = (uint32_t)((ncol + (lane & 7) + ((lane >> 4) & 1) * 8) * ARS
                              + ((lane >> 3) & 1) * 16);
    uint32_t wHb = sb + SM_WH + woff;
    uint32_t wLb = sb + SM_WL + woff;

    prefetchW(0);
    commitW();                 // W_j0 -> smem (no one reading yet)
    __syncthreads();           // covers prologue + W0
    prefetchW(1);

    float acc[2][4][4];

    // ---- j0: h = prelu(X@Wd1+b) -> R1 hi/lo ----
    zero_acc(acc);
    chain_gemm(sb + SM_R0H + aoff, wHb, wLb, acc);
    add_bias(acc, 0, ncol, tg);
    apply_prelu(acc, 0, ncol, tg);
    store_bf_hilo(smem + SM_R1H, acc, mrow, g, ncol, tg);
    __syncthreads();
    commitW();                 // W_j1
    __syncthreads();
    prefetchW(2);

    // ---- j1: rec = X + h@Wd2 + b -> R0 hi/lo ----
    zero_acc(acc);
    chain_gemm(sb + SM_R1H + aoff, wHb, wLb, acc);
    add_bias(acc, 1, ncol, tg);
    add_residual(smem + SM_R0H, acc, mrow, g, ncol, tg);
    store_bf_hilo(smem + SM_R0H, acc, mrow, g, ncol, tg);
    __syncthreads();
    commitW();                 // W_j2
    __syncthreads();

    // ---- j2: p = prelu(rec@Wp1+b) -> R1H fp16 single ----
    zero_acc(acc);
    chain_gemm(sb + SM_R0H + aoff, wHb, wLb, acc);
    add_bias(acc, 2, ncol, tg);
    apply_prelu(acc, 2, ncol, tg);
    store_f16(smem + SM_R1H, acc, mrow, g, ncol, tg);
    __syncthreads();

    // ---- stage pred W (4 chunks, fp16, into R1L..Wregion) + prefetch W_j7 ----
    {
        const uint4* src = (const uint4*)g_wx;
#pragma unroll
        for (int it = 0; it < 8; it++) {
            int i = it * NTHR + tid;        // 0..2047 uint4
            int c = i >> 9, w = i & 511;
            int row = w >> 3, c16 = w & 7;
            *(uint4*)(smem + SM_R1L + c * 9216 + row * ARS + c16 * 16) = src[i];
        }
    }
    prefetchW(3);
    __syncthreads();

    // ---- pred group: A=p cached in regs; 4 sync-free chunks ----
    {
        uint32_t aC[4][2][4];
        uint32_t aR1 = sb + SM_R1H + aoff;
#pragma unroll
        for (int kc = 0; kc < 4; kc++) {
            ldm4(aC[kc][0], aR1 + kc * 32);
            ldm4(aC[kc][1], aR1 + kc * 32 + 16 * ARS);
        }
#pragma unroll
        for (int c = 0; c < 4; c++) {
            zero_acc(acc);
            heavy_gemm(aC, sb + SM_R1L + c * 9216 + woff, acc);
            add_bias(acc, 3 + c, ncol, tg);
            int o0 = c * 64;
#pragma unroll
            for (int mt = 0; mt < 2; mt++) {
                int r = base + mrow + mt * 16 + g;
#pragma unroll
                for (int nt = 0; nt < 4; nt++) {
                    int col = o0 + ncol + nt * 8 + tg * 2;
                    float* cc = acc[mt][nt];
                    float* p0 = pred + (size_t)r * 255 + col;
                    float* p1 = pred + (size_t)(r + 8) * 255 + col;
                    if (col < 255) { p0[0] = cc[0]; p1[0] = cc[2]; }
                    if (col + 1 < 255) { p0[1] = cc[1]; p1[1] = cc[3]; }
                }
            }
        }
    }
    __syncthreads();
    commitW();                 // W_j7
    __syncthreads();
    prefetchW(4);

    // ---- j7: u1 = prelu([rec,bin]@Wu1+b) -> R1 hi/lo ----
    zero_acc(acc);
    chain_gemm(sb + SM_R0H + aoff, wHb, wLb, acc);
    add_bias(acc, 7, ncol, tg);
    {   // bin-concat tail (exact fp32)
#pragma unroll
        for (int mt = 0; mt < 2; mt++) {
            int rA = mrow + mt * 16 + g;
            int mA = smask[rA], mB = smask[rA + 8];
#pragma unroll
            for (int jj = 0; jj < 8; jj++) {
                bool bA = (mA >> jj) & 1, bB = (mB >> jj) & 1;
                if (bA | bB) {
#pragma unroll
                    for (int nt = 0; nt < 4; nt++) {
                        float2 t = *(const float2*)(wtail + jj * 64 + ncol + nt * 8 + tg * 2);
                        float* c = acc[mt][nt];
                        if (bA) { c[0] += 256.f * t.x; c[1] += 256.f * t.y; }
                        if (bB) { c[2] += 256.f * t.x; c[3] += 256.f * t.y; }
                    }
                }
            }
        }
    }
    apply_prelu(acc, 7, ncol, tg);
    store_bf_hilo(smem + SM_R1H, acc, mrow, g, ncol, tg);
    __syncthreads();
    commitW();                 // W_j8
    __syncthreads();
    prefetchW(5);

    // ---- j8: h2 = prelu(u1@Wu2+b) -> R0 hi/lo ----
    zero_acc(acc);
    chain_gemm(sb + SM_R1H + aoff, wHb, wLb, acc);
    add_bias(acc, 8, ncol, tg);
    apply_prelu(acc, 8, ncol, tg);
    store_bf_hilo(smem + SM_R0H, acc, mrow, g, ncol, tg);
    __syncthreads();
    commitW();                 // W_j9
    __syncthreads();

    // ---- j9: u = u1 + h2@Wu3 + b -> R1H fp16 single ----
    zero_acc(acc);
    chain_gemm(sb + SM_R0H + aoff, wHb, wLb, acc);
    add_bias(acc, 9, ncol, tg);
    add_residual(smem + SM_R1H, acc, mrow, g, ncol, tg);
    store_f16(smem + SM_R1H, acc, mrow, g, ncol, tg);
    __syncthreads();

    // ---- stage up4 W (8 chunks: 0-3 in R0, 4-7 in R1L..Wregion) ----
    {
        const uint4* src = (const uint4*)(g_wx + 4 * 4096);
#pragma unroll
        for (int it = 0; it < 16; it++) {
            int i = it * NTHR + tid;        // 0..4095 uint4
            int c = i >> 9, w = i & 511;
            int row = w >> 3, c16 = w & 7;
            uint32_t dst = (c < 4) ? (uint32_t)(c * 9216) : (uint32_t)(SM_R1L + (c - 4) * 9216);
            *(uint4*)(smem + dst + row * ARS + c16 * 16) = src[i];
        }
    }
    __syncthreads();

    // ---- up4 group: A=u cached in regs; 8 sync-free chunks -> newF scatter ----
    {
        uint32_t aC[4][2][4];
        uint32_t aR1 = sb + SM_R1H + aoff;
#pragma unroll
        for (int kc = 0; kc < 4; kc++) {
            ldm4(aC[kc][0], aR1 + kc * 32);
            ldm4(aC[kc][1], aR1 + kc * 32 + 16 * ARS);
        }
#pragma unroll
        for (int c = 0; c < 8; c++) {
            zero_acc(acc);
            uint32_t wb = (c < 4) ? (uint32_t)(c * 9216) : (uint32_t)(SM_R1L + (c - 4) * 9216);
            heavy_gemm(aC, sb + wb + woff, acc);
            add_bias(acc, 10 + c, ncol, tg);
#pragma unroll
            for (int mt = 0; mt < 2; mt++) {
                int rA = mrow + mt * 16 + g;
                bool okA = (smask[rA] >> c) & 1, okB = (smask[rA + 8] >> c) & 1;
                int iA = sinv[rA * 8 + c], iB = sinv[(rA + 8) * 8 + c];
#pragma unroll
                for (int nt = 0; nt < 4; nt++) {
                    int col = ncol + nt * 8 + tg * 2;
                    float* cc = acc[mt][nt];
                    if (okA) *(float2*)(newF + (size_t)iA * 64 + col) = make_float2(cc[0], cc[1]);
                    if (okB) *(float2*)(newF + (size_t)iB * 64 + col) = make_float2(cc[2], cc[3]);
                }
            }
        }
    }
}

extern "C" void kernel_launch(void* const* d_in, const int* in_sizes, int n_in,
                              void* d_out, int out_size) {
    const float* X   = (const float*)d_in[0];
    const int*   bin = (const int*)d_in[1];
    const int*   sel = (const int*)d_in[2];
    const float* Wd1 = (const float*)d_in[3];
    const float* bd1 = (const float*)d_in[4];
    const float* ad  = (const float*)d_in[5];
    const float* Wd2 = (const float*)d_in[6];
    const float* bd2 = (const float*)d_in[7];
    const float* Wp1 = (const float*)d_in[8];
    const float* bp1 = (const float*)d_in[9];
    const float* ap  = (const float*)d_in[10];
    const float* Wp2 = (const float*)d_in[11];
    const float* bp2 = (const float*)d_in[12];
    const float* Wu1 = (const float*)d_in[13];
    const float* bu1 = (const float*)d_in[14];
    const float* au1 = (const float*)d_in[15];
    const float* Wu2 = (const float*)d_in[16];
    const float* bu2 = (const float*)d_in[17];
    const float* au2 = (const float*)d_in[18];
    const float* Wu3 = (const float*)d_in[19];
    const float* bu3 = (const float*)d_in[20];
    const float* Wu4 = (const float*)d_in[21];
    const float* bu4 = (const float*)d_in[22];

    int n = in_sizes[0] / 64;
    int M = in_sizes[2];
    float* newF = (float*)d_out;
    float* pred = newF + (size_t)M * 64;
    float* oct  = pred + (size_t)n * 255;

    cudaFuncSetAttribute(k_main, cudaFuncAttributeMaxDynamicSharedMemorySize, SM_TOTAL);

    k_prep<<<18, 256>>>(Wd1, Wd2, Wp1, Wp2, Wu1, Wu2, Wu3, Wu4,
                        bd1, bd2, bp1, bp2, bu1, bu2, bu3, bu4,
                        ad, ap, au1, au2);
    if (M > 0) k0_inv<<<(M + 255) / 256, 256>>>(sel, M);
    k_main<<<n / TILEM, NTHR, SM_TOTAL>>>(X, bin, Wu1, pred, oct, newF);
}